// round 16
// baseline (speedup 1.0000x reference)
#include <cuda_runtime.h>
#include <stdint.h>

#define BATCH 2
#define Hh 128
#define Ww 128
#define HW (Hh * Ww)          // 16384 nodes
#define NE (2 * HW)           // 32768 edges per batch
#define NL 64                 // labels
#define WIN 512               // edges per block window (== k_scan blockDim)
#define TILE 4096             // sort tile
#define NTILES (NE / TILE)    // 8 tiles per batch
#define NOPAIR 0xffffffffu

// ---------------- static device scratch (no allocation allowed) ------------
__device__ __align__(256) unsigned long long g_keys[BATCH][NE];    // sort keys
__device__ __align__(256) unsigned short     g_u[BATCH][NE];
__device__ __align__(256) unsigned short     g_v[BATCH][NE];
__device__ __align__(256) float              g_a[BATCH][NE];
__device__ double    g_partial[BATCH];   // Sum over merges of tu*tv*a
__device__ long long g_same[BATCH];      // Sum_l>=1 C(N_l,2)

// ---------------- 1. build sort keys (descending affinity) -----------------
__global__ void k_build_keys(const float* __restrict__ aff) {
    int i = blockIdx.x * blockDim.x + threadIdx.x;   // b*NE + e
    if (i >= BATCH * NE) return;
    int b = i / NE;
    int e = i - b * NE;
    unsigned bits = __float_as_uint(aff[i]) | 0x80000000u;
    unsigned key  = ~bits;   // descending affinity under ascending uint sort
    g_keys[b][e] = ((unsigned long long)key << 32) | (unsigned)e;
}

// ---------------- 2a. local bitonic sort of each 4096-tile -----------------
__global__ void k_sort_local() {
    __shared__ unsigned long long sk[TILE];
    int b = blockIdx.x / NTILES;
    int t = blockIdx.x % NTILES;
    unsigned long long* base = g_keys[b] + t * TILE;

    for (int i = threadIdx.x; i < TILE; i += blockDim.x) sk[i] = base[i];
    __syncthreads();
    for (int k = 2; k <= TILE; k <<= 1) {
        for (int j = k >> 1; j > 0; j >>= 1) {
            for (int p = threadIdx.x; p < TILE / 2; p += blockDim.x) {
                int i = 2 * j * (p / j) + (p % j);
                int ixj = i + j;
                bool up = (((t * TILE + i) & k) == 0);
                unsigned long long A = sk[i], B = sk[ixj];
                if ((A > B) == up) { sk[i] = B; sk[ixj] = A; }
            }
            __syncthreads();
        }
    }
    for (int i = threadIdx.x; i < TILE; i += blockDim.x) base[i] = sk[i];
}

// ---------------- 2b. one global compare-exchange step (j >= TILE) ---------
__global__ void k_sort_gstep(int k, int j) {
    int p = blockIdx.x * blockDim.x + threadIdx.x;   // [0, BATCH*NE/2)
    int b = p / (NE / 2);
    int q = p - b * (NE / 2);
    int i = 2 * j * (q / j) + (q % j);
    int ixj = i + j;
    unsigned long long* keys = g_keys[b];
    unsigned long long A = keys[i], B = keys[ixj];
    bool up = ((i & k) == 0);
    if ((A > B) == up) { keys[i] = B; keys[ixj] = A; }
}

// ---------------- 2c. tiled finish of a merge stage (j <= TILE/2) ----------
__global__ void k_sort_tiled(int k) {
    __shared__ unsigned long long sk[TILE];
    int b = blockIdx.x / NTILES;
    int t = blockIdx.x % NTILES;
    unsigned long long* base = g_keys[b] + t * TILE;

    for (int i = threadIdx.x; i < TILE; i += blockDim.x) sk[i] = base[i];
    __syncthreads();
    for (int j = TILE >> 1; j > 0; j >>= 1) {
        for (int p = threadIdx.x; p < TILE / 2; p += blockDim.x) {
            int i = 2 * j * (p / j) + (p % j);
            int ixj = i + j;
            bool up = (((t * TILE + i) & k) == 0);
            unsigned long long A = sk[i], B = sk[ixj];
            if ((A > B) == up) { sk[i] = B; sk[ixj] = A; }
        }
        __syncthreads();
    }
    for (int i = threadIdx.x; i < TILE; i += blockDim.x) base[i] = sk[i];
}

// ---------------- 3. decode sorted edges into streaming arrays -------------
__global__ void k_decode(const float* __restrict__ aff) {
    int i = blockIdx.x * blockDim.x + threadIdx.x;   // b*NE + rank
    if (i >= BATCH * NE) return;
    int b = i / NE;
    int r = i - b * NE;
    unsigned long long kk = g_keys[b][r];
    int e = (int)(kk & 0xffffffffu);
    int c = (e >= HW) ? 1 : 0;
    int p = e - c * HW;
    int row = p >> 7, col = p & (Ww - 1);
    int u = 0, v = 0;                    // invalid boundary edge -> self edge (skip)
    if (!c) { if (row < Hh - 1) { u = p; v = p + Ww; } }
    else    { if (col < Ww - 1) { u = p; v = p + 1;  } }
    g_u[b][r] = (unsigned short)u;
    g_v[b][r] = (unsigned short)v;
    g_a[b][r] = aff[b * NE + e];
}

// ---------------- 4. same-label pair total: Sum_l>=1 C(N_l,2) --------------
__global__ void k_hist(const int* __restrict__ gt) {
    __shared__ int h[16][NL];     // per-warp sub-histograms
    int b = blockIdx.x;
    int w = threadIdx.x >> 5;
    int nw = blockDim.x >> 5;
    for (int i = threadIdx.x; i < 16 * NL; i += blockDim.x)
        ((int*)h)[i] = 0;
    __syncthreads();
    for (int i = threadIdx.x; i < HW; i += blockDim.x)
        atomicAdd(&h[w][gt[b * HW + i]], 1);
    __syncthreads();
    if (threadIdx.x < NL) {
        int l = threadIdx.x;
        int n = 0;
        for (int ww = 0; ww < nw; ww++) n += h[ww][l];
        h[0][l] = (l == 0) ? 0 : n;
    }
    __syncthreads();
    if (threadIdx.x == 0) {
        long long s = 0;
        for (int l = 1; l < NL; l++) {
            long long n = h[0][l];
            s += n * (n - 1) / 2;
        }
        g_same[b] = s;
    }
}

// ---------------- 5. claim Kruskal + winner star-walk (1 block/batch) ------
// Per round: pending edges find+claim; the winner (earliest claimant of both
// its roots) commits, then serially walks later window slots in index order,
// absorbing members (exclusive other root) / retiring cycle edges, breaking
// at the first non-committable edge. Single-thread walk = exact sequential
// counts, no cross-thread races. Leftovers iterate (rare).
__global__ void k_scan(const int* __restrict__ gt) {
    extern __shared__ unsigned short sh[];
    unsigned short* par   = sh;             // union-find parent
    unsigned short* szs   = sh + HW;        // component size
    unsigned short* nzs   = sh + 2 * HW;    // nonzero-label voxel count
    unsigned*       claim = (unsigned*)(sh + 3 * HW);  // monotone claim tags
    __shared__ unsigned      sRP[WIN];      // packed roots (ru | rv<<16), NOPAIR if inactive
    __shared__ float         sA[WIN];
    __shared__ unsigned char sDone[WIN];
    __shared__ double        sred[WIN];
    int b = blockIdx.x;
    int tid = threadIdx.x;

    for (int i = tid; i < HW; i += blockDim.x) {
        par[i] = (unsigned short)i;
        szs[i] = 1;
        nzs[i] = (gt[b * HW + i] != 0) ? 1 : 0;
        claim[i] = 0;
    }
    __syncthreads();

    const unsigned short* up_ = g_u[b];
    const unsigned short* vp_ = g_v[b];
    const float*          ap_ = g_a[b];

    double gacc = 0.0;    // thread-local Sum(tu*tv*a)
    unsigned rc = 1;      // monotone round counter

    for (int w0 = 0; w0 < NE; w0 += WIN) {
        int e = w0 + tid;
        int uu = up_[e], vv = vp_[e];
        float a = ap_[e];
        sA[tid] = a;
        bool pending = (uu != vv);

        int np = __syncthreads_count(pending ? 1 : 0);
        while (np) {
            unsigned tag = (rc << 10) | (unsigned)(1023 - tid);  // earlier edge = larger tag
            int ru = 0, rv = 0;
            sDone[tid] = 0;
            if (pending) {
                // parallel finds with path compression (no merges in flight ->
                // concurrent compression writes all store true roots)
                ru = uu; while (true) { int p = par[ru]; if (p == ru) break; ru = p; }
                { int x = uu; while (par[x] != ru) { int nx = par[x]; par[x] = (unsigned short)ru; x = nx; } }
                rv = vv; while (true) { int p = par[rv]; if (p == rv) break; rv = p; }
                { int x = vv; while (par[x] != rv) { int nx = par[x]; par[x] = (unsigned short)rv; x = nx; } }
                if (ru == rv) pending = false;   // non-merge: retire
                else { atomicMax(&claim[ru], tag); atomicMax(&claim[rv], tag); }
            }
            sRP[tid] = pending ? ((unsigned)ru | ((unsigned)rv << 16)) : NOPAIR;
            __syncthreads();                                 // bar1: claims + roots visible

            if (pending && claim[ru] == tag && claim[rv] == tag) {
                // winner: no earlier pending edge touches ru/rv
                int su = szs[ru], sv = szs[rv];
                int big   = (su >= sv) ? ru : rv;
                int small = ru + rv - big;
                par[small] = (unsigned short)big;
                int t = nzs[ru] + nzs[rv];
                int s = su + sv;
                gacc += (double)nzs[ru] * (double)nzs[rv] * (double)a;
                int R = big;
                // star walk: absorb later same-root edges in index order
                for (int j = tid + 1; j < WIN; j++) {
                    unsigned rp = sRP[j];
                    if (rp == NOPAIR) continue;
                    int r1 = (int)(rp & 0xffffu);
                    int r2 = (int)(rp >> 16);
                    bool t1 = (r1 == ru) | (r1 == rv);
                    bool t2 = (r2 == ru) | (r2 == rv);
                    if (!(t1 | t2)) continue;                // disjoint edge
                    if (t1 & t2) { sDone[j] = 1; continue; } // cycle within star: n=0
                    int X = t1 ? r2 : r1;                    // member's other root
                    if (claim[X] != ((rc << 10) | (unsigned)(1023 - j)))
                        break;                               // X contested -> stop star
                    int tX = nzs[X];
                    gacc += (double)tX * (double)t * (double)sA[j];
                    t += tX;
                    s += szs[X];
                    par[X] = (unsigned short)R;
                    sDone[j] = 1;
                }
                nzs[R] = (unsigned short)t;
                szs[R] = (unsigned short)s;
                pending = false;
            }
            __syncthreads();                                 // bar2: walks complete
            if (pending && sDone[tid]) pending = false;      // absorbed by a winner
            rc++;
            np = __syncthreads_count(pending ? 1 : 0);
        }
    }

    // block reduction of gacc
    sred[tid] = gacc;
    __syncthreads();
    for (int s = WIN / 2; s > 0; s >>= 1) {
        if (tid < s) sred[tid] += sred[tid + s];
        __syncthreads();
    }
    if (tid == 0) g_partial[b] = sred[0];
}

// ---------------- 6. finalize scalar ---------------------------------------
__global__ void k_final(float* __restrict__ out) {
    double t0 = g_partial[0] - (double)g_same[0];
    double t1 = g_partial[1] - (double)g_same[1];
    out[0] = (float)(-0.5 * (t0 + t1));
}

// ---------------------------------------------------------------------------
extern "C" void kernel_launch(void* const* d_in, const int* in_sizes, int n_in,
                              void* d_out, int out_size) {
    const float* aff = (const float*)d_in[0];      // [2,2,128,128] f32
    const int*   gt  = (const int*)d_in[1];        // [2,128,128] int32
    float* out = (float*)d_out;

    int shbytes = 3 * HW * (int)sizeof(unsigned short) + HW * (int)sizeof(unsigned);
    cudaFuncSetAttribute(k_scan, cudaFuncAttributeMaxDynamicSharedMemorySize, shbytes);

    k_build_keys<<<(BATCH * NE + 255) / 256, 256>>>(aff);

    // multi-block bitonic sort
    k_sort_local<<<BATCH * NTILES, 1024>>>();
    int gblocks = (BATCH * NE / 2) / 256;
    for (int k = TILE << 1; k <= NE; k <<= 1) {
        for (int j = k >> 1; j >= TILE; j >>= 1)
            k_sort_gstep<<<gblocks, 256>>>(k, j);
        k_sort_tiled<<<BATCH * NTILES, 1024>>>(k);
    }

    k_decode<<<(BATCH * NE + 255) / 256, 256>>>(aff);
    k_hist  <<<BATCH, 512>>>(gt);
    k_scan  <<<BATCH, WIN, shbytes>>>(gt);
    k_final <<<1, 1>>>(out);
}

// round 17
// speedup vs baseline: 1.1963x; 1.1963x over previous
#include <cuda_runtime.h>
#include <stdint.h>

#define BATCH 2
#define Hh 128
#define Ww 128
#define HW (Hh * Ww)          // 16384 nodes
#define NE (2 * HW)           // 32768 edges per batch
#define NL 64                 // labels
#define WIN 512               // edges per block window (== k_scan blockDim)
#define TILE 4096             // sort tile
#define NTILES (NE / TILE)    // 8 tiles per batch
#define FULLW 0xffffffffu

// ---------------- static device scratch (no allocation allowed) ------------
__device__ __align__(256) unsigned long long g_keys[BATCH][NE];    // sort keys
__device__ __align__(256) unsigned short     g_u[BATCH][NE];
__device__ __align__(256) unsigned short     g_v[BATCH][NE];
__device__ __align__(256) float              g_a[BATCH][NE];
__device__ double    g_partial[BATCH];   // Sum over merges of tu*tv*a
__device__ long long g_same[BATCH];      // Sum_l>=1 C(N_l,2)

// ---------------- 1. build sort keys (descending affinity) -----------------
__global__ void k_build_keys(const float* __restrict__ aff) {
    int i = blockIdx.x * blockDim.x + threadIdx.x;   // b*NE + e
    if (i >= BATCH * NE) return;
    int b = i / NE;
    int e = i - b * NE;
    unsigned bits = __float_as_uint(aff[i]) | 0x80000000u;
    unsigned key  = ~bits;   // descending affinity under ascending uint sort
    g_keys[b][e] = ((unsigned long long)key << 32) | (unsigned)e;
}

// ---------------- 2a. local bitonic sort of each 4096-tile -----------------
__global__ void k_sort_local() {
    __shared__ unsigned long long sk[TILE];
    int b = blockIdx.x / NTILES;
    int t = blockIdx.x % NTILES;
    unsigned long long* base = g_keys[b] + t * TILE;

    for (int i = threadIdx.x; i < TILE; i += blockDim.x) sk[i] = base[i];
    __syncthreads();
    for (int k = 2; k <= TILE; k <<= 1) {
        for (int j = k >> 1; j > 0; j >>= 1) {
            for (int p = threadIdx.x; p < TILE / 2; p += blockDim.x) {
                int i = 2 * j * (p / j) + (p % j);
                int ixj = i + j;
                bool up = (((t * TILE + i) & k) == 0);
                unsigned long long A = sk[i], B = sk[ixj];
                if ((A > B) == up) { sk[i] = B; sk[ixj] = A; }
            }
            __syncthreads();
        }
    }
    for (int i = threadIdx.x; i < TILE; i += blockDim.x) base[i] = sk[i];
}

// ---------------- 2b. one global compare-exchange step (j >= TILE) ---------
__global__ void k_sort_gstep(int k, int j) {
    int p = blockIdx.x * blockDim.x + threadIdx.x;   // [0, BATCH*NE/2)
    int b = p / (NE / 2);
    int q = p - b * (NE / 2);
    int i = 2 * j * (q / j) + (q % j);
    int ixj = i + j;
    unsigned long long* keys = g_keys[b];
    unsigned long long A = keys[i], B = keys[ixj];
    bool up = ((i & k) == 0);
    if ((A > B) == up) { keys[i] = B; keys[ixj] = A; }
}

// ---------------- 2c. tiled finish of a merge stage (j <= TILE/2) ----------
__global__ void k_sort_tiled(int k) {
    __shared__ unsigned long long sk[TILE];
    int b = blockIdx.x / NTILES;
    int t = blockIdx.x % NTILES;
    unsigned long long* base = g_keys[b] + t * TILE;

    for (int i = threadIdx.x; i < TILE; i += blockDim.x) sk[i] = base[i];
    __syncthreads();
    for (int j = TILE >> 1; j > 0; j >>= 1) {
        for (int p = threadIdx.x; p < TILE / 2; p += blockDim.x) {
            int i = 2 * j * (p / j) + (p % j);
            int ixj = i + j;
            bool up = (((t * TILE + i) & k) == 0);
            unsigned long long A = sk[i], B = sk[ixj];
            if ((A > B) == up) { sk[i] = B; sk[ixj] = A; }
        }
        __syncthreads();
    }
    for (int i = threadIdx.x; i < TILE; i += blockDim.x) base[i] = sk[i];
}

// ---------------- 3. decode sorted edges into streaming arrays -------------
__global__ void k_decode(const float* __restrict__ aff) {
    int i = blockIdx.x * blockDim.x + threadIdx.x;   // b*NE + rank
    if (i >= BATCH * NE) return;
    int b = i / NE;
    int r = i - b * NE;
    unsigned long long kk = g_keys[b][r];
    int e = (int)(kk & 0xffffffffu);
    int c = (e >= HW) ? 1 : 0;
    int p = e - c * HW;
    int row = p >> 7, col = p & (Ww - 1);
    int u = 0, v = 0;                    // invalid boundary edge -> self edge (skip)
    if (!c) { if (row < Hh - 1) { u = p; v = p + Ww; } }
    else    { if (col < Ww - 1) { u = p; v = p + 1;  } }
    g_u[b][r] = (unsigned short)u;
    g_v[b][r] = (unsigned short)v;
    g_a[b][r] = aff[b * NE + e];
}

// ---------------- 4. same-label pair total: Sum_l>=1 C(N_l,2) --------------
__global__ void k_hist(const int* __restrict__ gt) {
    __shared__ int h[16][NL];     // per-warp sub-histograms
    int b = blockIdx.x;
    int w = threadIdx.x >> 5;
    int nw = blockDim.x >> 5;
    for (int i = threadIdx.x; i < 16 * NL; i += blockDim.x)
        ((int*)h)[i] = 0;
    __syncthreads();
    for (int i = threadIdx.x; i < HW; i += blockDim.x)
        atomicAdd(&h[w][gt[b * HW + i]], 1);
    __syncthreads();
    if (threadIdx.x < NL) {
        int l = threadIdx.x;
        int n = 0;
        for (int ww = 0; ww < nw; ww++) n += h[ww][l];
        h[0][l] = (l == 0) ? 0 : n;
    }
    __syncthreads();
    if (threadIdx.x == 0) {
        long long s = 0;
        for (int l = 1; l < NL; l++) {
            long long n = h[0][l];
            s += n * (n - 1) / 2;
        }
        g_same[b] = s;
    }
}

// ---------------- 5. block-parallel claim Kruskal (1 block/batch) ----------
// Round-14 scheme (proven correct) + warp-aggregated claims: one atomicMax
// per (warp, root) group via __match_any_sync, killing same-address atomic
// serialization on the giant root.
__global__ void k_scan(const int* __restrict__ gt) {
    extern __shared__ unsigned short sh[];
    unsigned short* par   = sh;             // union-find parent
    unsigned short* szs   = sh + HW;        // component size
    unsigned short* nzs   = sh + 2 * HW;    // nonzero-label voxel count
    unsigned*       claim = (unsigned*)(sh + 3 * HW);  // monotone claim tags
    __shared__ double sred[WIN];
    int b = blockIdx.x;
    int tid = threadIdx.x;
    int lane = tid & 31;

    for (int i = tid; i < HW; i += blockDim.x) {
        par[i] = (unsigned short)i;
        szs[i] = 1;
        nzs[i] = (gt[b * HW + i] != 0) ? 1 : 0;
        claim[i] = 0;
    }
    __syncthreads();

    const unsigned short* up_ = g_u[b];
    const unsigned short* vp_ = g_v[b];
    const float*          ap_ = g_a[b];

    double gacc = 0.0;    // thread-local Sum(tu*tv*a)
    unsigned rc = 1;      // monotone round counter

    for (int w0 = 0; w0 < NE; w0 += WIN) {
        int e = w0 + tid;
        int uu = up_[e], vv = vp_[e];
        float a = ap_[e];
        bool pending = (uu != vv);

        int np = __syncthreads_count(pending ? 1 : 0);
        while (np) {
            unsigned tag = (rc << 10) | (unsigned)(1023 - tid);  // earlier edge = larger tag
            int ru = 0, rv = 0;
            if (pending) {
                // parallel finds with path compression (no merges in flight ->
                // concurrent compression writes all store true roots)
                ru = uu; while (true) { int p = par[ru]; if (p == ru) break; ru = p; }
                { int x = uu; while (par[x] != ru) { int nx = par[x]; par[x] = (unsigned short)ru; x = nx; } }
                rv = vv; while (true) { int p = par[rv]; if (p == rv) break; rv = p; }
                { int x = vv; while (par[x] != rv) { int nx = par[x]; par[x] = (unsigned short)rv; x = nx; } }
                if (ru == rv) pending = false;   // non-merge: retire
            }
            // warp-aggregated claims: lanes are tid-ordered, so the lowest
            // lane in each equal-root group holds the group's max tag and is
            // the only one that needs to claim that root.
            unsigned ku = pending ? (unsigned)ru : (0x20000u + (unsigned)tid);
            unsigned kv = pending ? (unsigned)rv : (0x30000u + (unsigned)tid);
            unsigned mu = __match_any_sync(FULLW, ku);
            unsigned mv = __match_any_sync(FULLW, kv);
            if (pending) {
                if (lane == __ffs(mu) - 1) atomicMax(&claim[ru], tag);
                if (lane == __ffs(mv) - 1) atomicMax(&claim[rv], tag);
            }
            __syncthreads();                                 // bar1: claims visible
            if (pending && claim[ru] == tag && claim[rv] == tag) {
                // winner: no earlier pending edge touches ru/rv
                int su = szs[ru], sv = szs[rv];
                int big   = (su >= sv) ? ru : rv;
                int small = ru + rv - big;
                par[small] = (unsigned short)big;
                int tu = nzs[ru], tv = nzs[rv];
                szs[big] = (unsigned short)(su + sv);
                nzs[big] = (unsigned short)(tu + tv);
                gacc += (double)(tu * tv) * (double)a;
                pending = false;
            }
            rc++;
            np = __syncthreads_count(pending ? 1 : 0);       // bar2: commits visible
        }
    }

    // block reduction of gacc
    sred[tid] = gacc;
    __syncthreads();
    for (int s = WIN / 2; s > 0; s >>= 1) {
        if (tid < s) sred[tid] += sred[tid + s];
        __syncthreads();
    }
    if (tid == 0) g_partial[b] = sred[0];
}

// ---------------- 6. finalize scalar ---------------------------------------
__global__ void k_final(float* __restrict__ out) {
    double t0 = g_partial[0] - (double)g_same[0];
    double t1 = g_partial[1] - (double)g_same[1];
    out[0] = (float)(-0.5 * (t0 + t1));
}

// ---------------------------------------------------------------------------
extern "C" void kernel_launch(void* const* d_in, const int* in_sizes, int n_in,
                              void* d_out, int out_size) {
    const float* aff = (const float*)d_in[0];      // [2,2,128,128] f32
    const int*   gt  = (const int*)d_in[1];        // [2,128,128] int32
    float* out = (float*)d_out;

    int shbytes = 3 * HW * (int)sizeof(unsigned short) + HW * (int)sizeof(unsigned);
    cudaFuncSetAttribute(k_scan, cudaFuncAttributeMaxDynamicSharedMemorySize, shbytes);

    k_build_keys<<<(BATCH * NE + 255) / 256, 256>>>(aff);

    // multi-block bitonic sort
    k_sort_local<<<BATCH * NTILES, 1024>>>();
    int gblocks = (BATCH * NE / 2) / 256;
    for (int k = TILE << 1; k <= NE; k <<= 1) {
        for (int j = k >> 1; j >= TILE; j >>= 1)
            k_sort_gstep<<<gblocks, 256>>>(k, j);
        k_sort_tiled<<<BATCH * NTILES, 1024>>>(k);
    }

    k_decode<<<(BATCH * NE + 255) / 256, 256>>>(aff);
    k_hist  <<<BATCH, 512>>>(gt);
    k_scan  <<<BATCH, WIN, shbytes>>>(gt);
    k_final <<<1, 1>>>(out);
}